// round 16
// baseline (speedup 1.0000x reference)
#include <cuda_runtime.h>
#include <cstddef>

// ---------------------------------------------------------------------------
// RVQECell simulator, N = 19 qubits, B = 32.
// Bit layout of a state index (19 bits):
//   bits 18..13 : inout lanes 0..5   (lane l -> bit 18-l)
//   bits 12..1  : work  lanes 6..17
//   bit  0      : ancilla lane 18
// float2 packing: the two ancilla values (bit 0) live in .x/.y of one float2,
// so a chunk of 2^13 amplitudes = 4096 float2, indexed by fi = bits 12..1.
// ---------------------------------------------------------------------------

static __device__ float2 g_wtab[48 * 131072];   // work-neuron angle tables (cos,sin)
static __device__ float2 g_otab[6 * 131072];    // output-neuron angle tables
static __device__ float2 g_utab[36];            // unitary-layer (cos,sin) per (stage,lane)
static __device__ float  g_scratch[32 * 524288]; // state after kernel layers

// ---------------------------------------------------------------------------
// Angle-table precompute.
// phi(x) = pi/2 + sum_i th1[i] b_i + sum_{i<j} th2[i][j] b_i b_j,
// b_i = bit (16-i) of x  (controls in ascending lane order, MSB first).
// ORDER=2 -> alpha = atan2(sin^2 phi, cos^2 phi):
//   cosA = cos^2/r, sinA = sin^2/r, r = sqrt(cos^4 + sin^4).
// ---------------------------------------------------------------------------
__global__ void __launch_bounds__(256) tab_kernel(
    const float* __restrict__ w_in1, const float* __restrict__ w_in2,
    const float* __restrict__ w_k1,  const float* __restrict__ w_k2,
    const float* __restrict__ w_out1, const float* __restrict__ w_out2)
{
    const int n = blockIdx.y;          // neuron id 0..53
    __shared__ float th1[17];
    __shared__ float th2[289];
    const float *p1, *p2;
    float2* dst;
    if (n < 12)      { p1 = w_in1  + n * 17;        p2 = w_in2  + n * 289;        dst = g_wtab + (size_t)n * 131072; }
    else if (n < 48) { p1 = w_k1   + (n - 12) * 17; p2 = w_k2   + (n - 12) * 289; dst = g_wtab + (size_t)n * 131072; }
    else             { p1 = w_out1 + (n - 48) * 17; p2 = w_out2 + (n - 48) * 289; dst = g_otab + (size_t)(n - 48) * 131072; }

    for (int i = threadIdx.x; i < 17; i += 256)  th1[i] = p1[i];
    for (int i = threadIdx.x; i < 289; i += 256) th2[i] = p2[i];
    __syncthreads();

    const unsigned x = blockIdx.x * 256u + threadIdx.x;   // 0 .. 2^17-1
    float phi = 1.57079632679489662f;                     // pi/2 bias
    #pragma unroll
    for (int i = 0; i < 17; i++) {
        float acc = th1[i];
        #pragma unroll
        for (int j = i + 1; j < 17; j++)
            if ((x >> (16 - j)) & 1u) acc += th2[i * 17 + j];
        if ((x >> (16 - i)) & 1u) phi += acc;
    }
    float s, c;
    sincosf(phi, &s, &c);
    const float c2 = c * c, s2 = s * s;
    const float rn = rsqrtf(fmaxf(c2 * c2 + s2 * s2, 1e-30f));
    dst[x] = make_float2(c2 * rn, s2 * rn);
}

__global__ void utab_kernel(const float* __restrict__ w_u)
{
    const int i = threadIdx.x;
    if (i < 36) {
        float s, c;
        sincosf(w_u[i], &s, &c);
        g_utab[i] = make_float2(c, s);
    }
}

// ---------------------------------------------------------------------------
// Register-resident chunk engine.
// Thread layout: fi = (i<<8) | tid, i = 0..15 register slots, tid = 0..255.
//   target bit U in 8..11 : register pairing (slot bit U-8)
//   target bit U in 5..7  : shared-memory exchange (warp bits)
//   target bit U in 0..4  : __shfl_xor pairing (lane bits)
// Control index for a work neuron: x = (hi6 << 11) | removebit(fi, U).
// ---------------------------------------------------------------------------
__device__ __forceinline__ void rot2(float2& a, float2& b, float c, float s)
{
    float2 na, nb;
    na.x = c * a.x - s * b.x;  na.y = c * a.y - s * b.y;
    nb.x = s * a.x + c * b.x;  nb.y = s * a.y + c * b.y;
    a = na; b = nb;
}

template<int U>
__device__ __forceinline__ void neuron_op(float2 (&v)[16], const float2* __restrict__ tab,
                                          unsigned xbase, unsigned tid, float2* sm)
{
    if constexpr (U >= 8) {
        constexpr int d = U - 8;
        #pragma unroll
        for (int i = 0; i < 16; i++) {
            if (i & (1 << d)) continue;
            const unsigned fi = ((unsigned)i << 8) | tid;
            const unsigned k  = ((fi >> (U + 1)) << U) | (fi & ((1u << U) - 1u));
            const float2 cs = __ldg(tab + (xbase | k));
            rot2(v[i], v[i | (1 << d)], cs.x, cs.y);
        }
    } else if constexpr (U >= 5) {
        __syncthreads();                       // prior reads of sm done
        #pragma unroll
        for (int i = 0; i < 16; i++) sm[((unsigned)i << 8) | tid] = v[i];
        __syncthreads();
        const int beta = (tid >> U) & 1u;
        #pragma unroll
        for (int i = 0; i < 16; i++) {
            const unsigned fi = ((unsigned)i << 8) | tid;
            const float2 p = sm[fi ^ (1u << U)];
            const unsigned k = ((fi >> (U + 1)) << U) | (fi & ((1u << U) - 1u));
            const float2 cs = __ldg(tab + (xbase | k));
            const float se = beta ? cs.y : -cs.y;
            v[i].x = cs.x * v[i].x + se * p.x;
            v[i].y = cs.x * v[i].y + se * p.y;
        }
    } else {
        const int beta = (tid >> U) & 1u;
        #pragma unroll
        for (int i = 0; i < 16; i++) {
            const unsigned fi = ((unsigned)i << 8) | tid;
            const float px = __shfl_xor_sync(0xffffffffu, v[i].x, 1 << U);
            const float py = __shfl_xor_sync(0xffffffffu, v[i].y, 1 << U);
            const unsigned k = ((fi >> (U + 1)) << U) | (fi & ((1u << U) - 1u));
            const float2 cs = __ldg(tab + (xbase | k));
            const float se = beta ? cs.y : -cs.y;
            v[i].x = cs.x * v[i].x + se * px;
            v[i].y = cs.x * v[i].y + se * py;
        }
    }
}

template<int U>
__device__ __forceinline__ void urot(float2 (&v)[16], float c, float s, unsigned tid, float2* sm)
{
    if constexpr (U >= 8) {
        constexpr int d = U - 8;
        #pragma unroll
        for (int i = 0; i < 16; i++) {
            if (i & (1 << d)) continue;
            rot2(v[i], v[i | (1 << d)], c, s);
        }
    } else if constexpr (U >= 5) {
        __syncthreads();
        #pragma unroll
        for (int i = 0; i < 16; i++) sm[((unsigned)i << 8) | tid] = v[i];
        __syncthreads();
        const float se = ((tid >> U) & 1u) ? s : -s;
        #pragma unroll
        for (int i = 0; i < 16; i++) {
            const float2 p = sm[(((unsigned)i << 8) | tid) ^ (1u << U)];
            v[i].x = c * v[i].x + se * p.x;
            v[i].y = c * v[i].y + se * p.y;
        }
    } else {
        const float se = ((tid >> U) & 1u) ? s : -s;
        #pragma unroll
        for (int i = 0; i < 16; i++) {
            const float px = __shfl_xor_sync(0xffffffffu, v[i].x, 1 << U);
            const float py = __shfl_xor_sync(0xffffffffu, v[i].y, 1 << U);
            v[i].x = c * v[i].x + se * px;
            v[i].y = c * v[i].y + se * py;
        }
    }
}

// One neuron layer, lanes j=0..11 in order -> target bit U = 11-j.
#define NLAYER(TB)                                                 \
    neuron_op<11>(v, (TB) +  0 * 131072, xbase, tid, sm);          \
    neuron_op<10>(v, (TB) +  1 * 131072, xbase, tid, sm);          \
    neuron_op< 9>(v, (TB) +  2 * 131072, xbase, tid, sm);          \
    neuron_op< 8>(v, (TB) +  3 * 131072, xbase, tid, sm);          \
    neuron_op< 7>(v, (TB) +  4 * 131072, xbase, tid, sm);          \
    neuron_op< 6>(v, (TB) +  5 * 131072, xbase, tid, sm);          \
    neuron_op< 5>(v, (TB) +  6 * 131072, xbase, tid, sm);          \
    neuron_op< 4>(v, (TB) +  7 * 131072, xbase, tid, sm);          \
    neuron_op< 3>(v, (TB) +  8 * 131072, xbase, tid, sm);          \
    neuron_op< 2>(v, (TB) +  9 * 131072, xbase, tid, sm);          \
    neuron_op< 1>(v, (TB) + 10 * 131072, xbase, tid, sm);          \
    neuron_op< 0>(v, (TB) + 11 * 131072, xbase, tid, sm);

__global__ void __launch_bounds__(256) main_kernel(const float* __restrict__ batch,
                                                   const int* __restrict__ inputs)
{
    __shared__ float2 sm[4096];
    const unsigned tid = threadIdx.x;
    const unsigned hi6 = blockIdx.x;   // 0..63
    const unsigned b   = blockIdx.y;   // 0..31

    unsigned fhi = 0;                  // bitflip mask restricted to inout bits
    #pragma unroll
    for (int i = 0; i < 6; i++) fhi |= ((unsigned)inputs[b * 6 + i] & 1u) << (5 - i);

    // load chunk; first BitFlipLayer folded into the source hi6 index
    const float2* src = reinterpret_cast<const float2*>(batch)
                      + ((size_t)b << 18) + ((size_t)(hi6 ^ fhi) << 12);
    float2 v[16];
    #pragma unroll
    for (int i = 0; i < 16; i++) v[i] = src[((unsigned)i << 8) | tid];

    const unsigned xbase = hi6 << 11;

    // input layer (tables 0..11)
    NLAYER(g_wtab)

    // kernel layers: 3 x (UnitaryLayer + 12 neurons)
    #pragma unroll 1
    for (int st = 0; st < 3; st++) {
        const float2* ut = g_utab + st * 12;   // lane j -> ut[j], target U = 11-j
        urot<11>(v, ut[0].x,  ut[0].y,  tid, sm);
        urot<10>(v, ut[1].x,  ut[1].y,  tid, sm);
        urot< 9>(v, ut[2].x,  ut[2].y,  tid, sm);
        urot< 8>(v, ut[3].x,  ut[3].y,  tid, sm);
        urot< 7>(v, ut[4].x,  ut[4].y,  tid, sm);
        urot< 6>(v, ut[5].x,  ut[5].y,  tid, sm);
        urot< 5>(v, ut[6].x,  ut[6].y,  tid, sm);
        urot< 4>(v, ut[7].x,  ut[7].y,  tid, sm);
        urot< 3>(v, ut[8].x,  ut[8].y,  tid, sm);
        urot< 2>(v, ut[9].x,  ut[9].y,  tid, sm);
        urot< 1>(v, ut[10].x, ut[10].y, tid, sm);
        urot< 0>(v, ut[11].x, ut[11].y, tid, sm);
        const float2* tb = g_wtab + (size_t)(12 + st * 12) * 131072;
        NLAYER(tb)
    }

    float2* dst = reinterpret_cast<float2*>(g_scratch)
                + ((size_t)b << 18) + ((size_t)hi6 << 12);
    #pragma unroll
    for (int i = 0; i < 16; i++) dst[((unsigned)i << 8) | tid] = v[i];
}

// ---------------------------------------------------------------------------
// Output layer: second bitflip (folded into load), 6 neurons on inout bits,
// psi write-out and marginal probabilities over the inout register.
// Tile: all 64 hi6 values x 128 contiguous low-bit amplitudes (32 KB smem).
// ---------------------------------------------------------------------------
__global__ void __launch_bounds__(256) out_kernel(float* __restrict__ out,
                                                  const int* __restrict__ inputs)
{
    __shared__ float tsm[64 * 128];
    __shared__ float sprob[64];
    const unsigned tid  = threadIdx.x;
    const unsigned tile = blockIdx.x;   // 0..63 (low13 in chunks of 128 floats)
    const unsigned b    = blockIdx.y;   // 0..31

    unsigned fhi = 0;
    #pragma unroll
    for (int i = 0; i < 6; i++) fhi |= ((unsigned)inputs[b * 6 + i] & 1u) << (5 - i);

    const float* src = g_scratch + ((size_t)b << 19);
    #pragma unroll
    for (int it = 0; it < 8; it++) {
        const unsigned idx = it * 256u + tid;          // float4 index 0..2047
        const unsigned row = idx >> 5, c4 = idx & 31u;
        const float4 val = *reinterpret_cast<const float4*>(
            src + ((size_t)(row ^ fhi) << 13) + tile * 128u + c4 * 4u);
        *reinterpret_cast<float4*>(tsm + row * 128u + c4 * 4u) = val;
    }
    __syncthreads();

    const unsigned lowbase = tile << 6;   // fi12 base (float2 units)
    #pragma unroll
    for (int j = 0; j < 6; j++) {         // output neuron on inout lane j
        const int h = 5 - j;              // target bit within hi6
        const float2* tab = g_otab + (size_t)j * 131072;
        #pragma unroll
        for (int it = 0; it < 8; it++) {
            const unsigned k  = it * 256u + tid;      // pair item 0..2047
            const unsigned c2 = k & 63u;              // float2 column
            const unsigned rp = k >> 6;               // compressed non-target hi bits
            const unsigned r0 = ((rp >> h) << (h + 1)) | (rp & ((1u << h) - 1u));
            const unsigned r1 = r0 | (1u << h);
            const unsigned x  = (rp << 12) | (lowbase + c2);
            const float2 cs = __ldg(tab + x);
            float2* a  = reinterpret_cast<float2*>(tsm + r0 * 128u) + c2;
            float2* bb = reinterpret_cast<float2*>(tsm + r1 * 128u) + c2;
            const float2 A = *a, B = *bb;
            float2 nA, nB;
            nA.x = cs.x * A.x - cs.y * B.x;  nA.y = cs.x * A.y - cs.y * B.y;
            nB.x = cs.y * A.x + cs.x * B.x;  nB.y = cs.y * A.y + cs.x * B.y;
            *a = nA; *bb = nB;
        }
        __syncthreads();
    }

    // psi write + per-row probability partials (one warp per (row,it): all 32
    // lanes of a warp share the same row here, so a warp reduction suffices).
    float* psi = out + 2048 + ((size_t)b << 19);
    #pragma unroll
    for (int it = 0; it < 8; it++) {
        const unsigned idx = it * 256u + tid;
        const unsigned row = idx >> 5, c4 = idx & 31u;
        const float4 val = *reinterpret_cast<const float4*>(tsm + row * 128u + c4 * 4u);
        *reinterpret_cast<float4*>(psi + ((size_t)row << 13) + tile * 128u + c4 * 4u) = val;
        float ssum = val.x * val.x + val.y * val.y + val.z * val.z + val.w * val.w;
        #pragma unroll
        for (int o = 16; o; o >>= 1) ssum += __shfl_down_sync(0xffffffffu, ssum, o);
        if ((tid & 31u) == 0) sprob[row] = ssum;   // unique row per (warp,it)
    }
    __syncthreads();
    if (tid < 64) atomicAdd(out + b * 64u + tid, sprob[tid]);
}

// ---------------------------------------------------------------------------
// Launch: d_in order = batch, w_in1, w_in2, w_u, w_k1, w_k2, w_out1, w_out2,
// inputs. d_out = [probs (32*64 floats)] ++ [psi (32*2^19 floats)].
// ---------------------------------------------------------------------------
extern "C" void kernel_launch(void* const* d_in, const int* in_sizes, int n_in,
                              void* d_out, int out_size)
{
    const float* batch  = (const float*)d_in[0];
    const float* w_in1  = (const float*)d_in[1];
    const float* w_in2  = (const float*)d_in[2];
    const float* w_u    = (const float*)d_in[3];
    const float* w_k1   = (const float*)d_in[4];
    const float* w_k2   = (const float*)d_in[5];
    const float* w_out1 = (const float*)d_in[6];
    const float* w_out2 = (const float*)d_in[7];
    const int*   inputs = (const int*)d_in[8];
    float* out = (float*)d_out;

    cudaMemsetAsync(out, 0, 32 * 64 * sizeof(float));
    tab_kernel<<<dim3(512, 54), 256>>>(w_in1, w_in2, w_k1, w_k2, w_out1, w_out2);
    utab_kernel<<<1, 64>>>(w_u);
    main_kernel<<<dim3(64, 32), 256>>>(batch, inputs);
    out_kernel<<<dim3(64, 32), 256>>>(out, inputs);
}